// round 17
// baseline (speedup 1.0000x reference)
#include <cuda_runtime.h>
#include <cuda_bf16.h>
#include <cstdint>

#define NUM_GRIDS 8

__device__ __forceinline__ float tanh_approx(float x) {
    float y;
    asm("tanh.approx.f32 %0, %1;" : "=f"(y) : "f"(x));
    return y;
}

// th = tanh(fma(x, inv, -g*inv)); out = 1 - th*th
__device__ __forceinline__ float bump_fma(float x, float inv, float negGI) {
    const float th = tanh_approx(fmaf(x, inv, negGI));
    return 1.0f - th * th;
}

// Single launch (no setup kernel: its ~3us replay tax outweighed the
// prologue it saved). One thread per input element:
//   in : 1x LDG.32 (warp = 128 B coalesced)
//   out: 1x STG.256 (warp = 1024 B contiguous, evict-first)
// Prologue: inv + grid loads (L1 broadcast) -> c[j] = g[j] * (-inv),
// body uses the FMA form so each basis is FFMA + MUFU + FFMA.
__global__ __launch_bounds__(256)
void rswaf_kernel(const float*  __restrict__ x,
                  const float4* __restrict__ grid,   // [8] floats = 2 float4
                  const float*  __restrict__ inv_den,
                  float*        __restrict__ out,
                  int n) {
    const int e = blockIdx.x * blockDim.x + threadIdx.x;
    if (e >= n) return;

    const float inv = __ldg(inv_den);
    const float niv = -inv;

    const float4 gA = __ldg(grid + 0);
    const float4 gB = __ldg(grid + 1);
    const float c0 = gA.x * niv, c1 = gA.y * niv, c2 = gA.z * niv, c3 = gA.w * niv;
    const float c4 = gB.x * niv, c5 = gB.y * niv, c6 = gB.z * niv, c7 = gB.w * niv;

    const float xi = __ldcs(x + e);

    const float r0 = bump_fma(xi, inv, c0);
    const float r1 = bump_fma(xi, inv, c1);
    const float r2 = bump_fma(xi, inv, c2);
    const float r3 = bump_fma(xi, inv, c3);
    const float r4 = bump_fma(xi, inv, c4);
    const float r5 = bump_fma(xi, inv, c5);
    const float r6 = bump_fma(xi, inv, c6);
    const float r7 = bump_fma(xi, inv, c7);

    float* dst = out + (long long)e * NUM_GRIDS;      // 32B-aligned
    asm volatile(
        "st.global.cs.v8.f32 [%0], {%1,%2,%3,%4,%5,%6,%7,%8};"
        :: "l"(dst),
           "f"(r0), "f"(r1), "f"(r2), "f"(r3),
           "f"(r4), "f"(r5), "f"(r6), "f"(r7)
        : "memory");
}

extern "C" void kernel_launch(void* const* d_in, const int* in_sizes, int n_in,
                              void* d_out, int out_size) {
    const float* x       = (const float*)d_in[0];   // [16,64,128,128] fp32
    const float* grid    = (const float*)d_in[1];   // [8] fp32
    const float* inv_den = (const float*)d_in[2];   // scalar fp32
    float* out = (float*)d_out;                     // [...,8] fp32

    const int n = in_sizes[0];                      // 16,777,216

    const int threads = 256;
    const int blocks  = (n + threads - 1) / threads;   // 65536

    rswaf_kernel<<<blocks, threads>>>(
        x, (const float4*)grid, inv_den, out, n);
}